// round 1
// baseline (speedup 1.0000x reference)
#include <cuda_runtime.h>
#include <cuda_bf16.h>

// MaskedAttention: B=4, S=1024, WIDTH=1024, H=16, DH=64
// softmax over the HEAD axis (axis=1), mask broadcast over heads.

#define B_ 4
#define S_ 1024
#define W_ 1024
#define H_ 16
#define DH_ 64
#define M_ (B_ * S_)          // 4096 rows

// Scratch (device globals: allocation-free rule)
__device__ float g_q[M_ * W_];
__device__ float g_k[M_ * W_];
__device__ float g_v[M_ * W_];
__device__ float g_x[M_ * W_];
__device__ float g_qk[(size_t)B_ * H_ * S_ * S_];   // 256 MB scores/attn

// ---------------------------------------------------------------------------
// Generic GEMM with bias: C[m,n] = sum_k A[m,k] * Wt[n,k] + bias[n]
// Tiles: 64x64, K-tile 16, 256 threads, 4x4 microtile.
// ---------------------------------------------------------------------------
__global__ void gemm_bias_kernel(const float* __restrict__ A,
                                 const float* __restrict__ Wt,
                                 const float* __restrict__ bias,
                                 float* __restrict__ C,
                                 int M, int N, int K) {
    __shared__ float As[16][65];
    __shared__ float Ws[16][65];
    const int tid = threadIdx.x;
    const int tx = tid & 15, ty = tid >> 4;
    const int row0 = blockIdx.y * 64;
    const int col0 = blockIdx.x * 64;

    float acc[4][4] = {};
    for (int k0 = 0; k0 < K; k0 += 16) {
        #pragma unroll
        for (int idx = tid; idx < 64 * 16; idx += 256) {
            int m = idx >> 4, kk = idx & 15;
            As[kk][m] = A[(size_t)(row0 + m) * K + k0 + kk];
        }
        #pragma unroll
        for (int idx = tid; idx < 64 * 16; idx += 256) {
            int n = idx >> 4, kk = idx & 15;
            Ws[kk][n] = Wt[(size_t)(col0 + n) * K + k0 + kk];
        }
        __syncthreads();
        #pragma unroll
        for (int kk = 0; kk < 16; kk++) {
            float a[4], w[4];
            #pragma unroll
            for (int i = 0; i < 4; i++) a[i] = As[kk][ty * 4 + i];
            #pragma unroll
            for (int j = 0; j < 4; j++) w[j] = Ws[kk][tx * 4 + j];
            #pragma unroll
            for (int i = 0; i < 4; i++)
                #pragma unroll
                for (int j = 0; j < 4; j++)
                    acc[i][j] += a[i] * w[j];
        }
        __syncthreads();
    }
    #pragma unroll
    for (int j = 0; j < 4; j++) {
        float bj = bias[col0 + tx * 4 + j];
        #pragma unroll
        for (int i = 0; i < 4; i++)
            C[(size_t)(row0 + ty * 4 + i) * N + col0 + tx * 4 + j] = acc[i][j] + bj;
    }
}

// ---------------------------------------------------------------------------
// QK^T per (b,h): out[bh,i,j] = scale * sum_d Q[b,i,h*64+d] * K[b,j,h*64+d]
// 64x64 tile, K-dim = DH = 64 loaded fully into smem.
// ---------------------------------------------------------------------------
__global__ void qk_kernel(const float* __restrict__ q,
                          const float* __restrict__ k,
                          float* __restrict__ out) {
    __shared__ float Qs[64][65];
    __shared__ float Ks[64][65];
    const int bh = blockIdx.z;
    const int b = bh >> 4, h = bh & 15;
    const int i0 = blockIdx.y * 64, j0 = blockIdx.x * 64;
    const int tid = threadIdx.x;
    const int tx = tid & 15, ty = tid >> 4;

    const float* qb = q + (size_t)b * S_ * W_ + h * DH_;
    const float* kb = k + (size_t)b * S_ * W_ + h * DH_;

    #pragma unroll
    for (int idx = tid; idx < 4096; idx += 256) {
        int m = idx >> 6, d = idx & 63;
        Qs[d][m] = qb[(size_t)(i0 + m) * W_ + d];
        Ks[d][m] = kb[(size_t)(j0 + m) * W_ + d];
    }
    __syncthreads();

    float acc[4][4] = {};
    #pragma unroll
    for (int d = 0; d < 64; d++) {
        float a[4], c[4];
        #pragma unroll
        for (int i = 0; i < 4; i++) a[i] = Qs[d][ty * 4 + i];
        #pragma unroll
        for (int j = 0; j < 4; j++) c[j] = Ks[d][tx * 4 + j];
        #pragma unroll
        for (int i = 0; i < 4; i++)
            #pragma unroll
            for (int j = 0; j < 4; j++)
                acc[i][j] += a[i] * c[j];
    }

    float* ob = out + ((size_t)bh * S_ + i0) * S_ + j0;
    const float scale = 0.125f;  // 1/sqrt(64)
    #pragma unroll
    for (int i = 0; i < 4; i++)
        #pragma unroll
        for (int j = 0; j < 4; j++)
            ob[(size_t)(ty * 4 + i) * S_ + tx * 4 + j] = acc[i][j] * scale;
}

// ---------------------------------------------------------------------------
// Softmax over the HEAD axis, in place on g_qk.
// mask is [B,1,S,S] broadcast over h: mask==0 -> all heads -1e9 -> uniform 1/16.
// One thread per (b,q,k); the 16 head values are at stride S*S.
// ---------------------------------------------------------------------------
__global__ void head_softmax_kernel(const int* __restrict__ mask,
                                    float* __restrict__ qk) {
    const int idx = blockIdx.x * blockDim.x + threadIdx.x;  // over B*S*S
    if (idx >= B_ * S_ * S_) return;
    const int b = idx >> 20;            // S*S = 1M
    const int qs = idx & ((1 << 20) - 1);
    const size_t base = (size_t)b * H_ * S_ * S_ + qs;
    const size_t hs = (size_t)S_ * S_;

    if (mask[idx] == 0) {
        #pragma unroll
        for (int h = 0; h < H_; h++) qk[base + h * hs] = 1.0f / 16.0f;
        return;
    }
    float v[H_];
    float mx = -1e30f;
    #pragma unroll
    for (int h = 0; h < H_; h++) {
        v[h] = qk[base + h * hs];
        mx = fmaxf(mx, v[h]);
    }
    float s = 0.0f;
    #pragma unroll
    for (int h = 0; h < H_; h++) {
        v[h] = __expf(v[h] - mx);
        s += v[h];
    }
    const float inv = 1.0f / s;
    #pragma unroll
    for (int h = 0; h < H_; h++) qk[base + h * hs] = v[h] * inv;
}

// ---------------------------------------------------------------------------
// AV per (b,h): x[b,q,h*64+d] = sum_k attn[bh,q,k] * v[b,k,h*64+d]
// Writes directly into the [B,S,WIDTH] layout (transpose fused).
// 64(q) x 64(d) tile, K-tile 32.
// ---------------------------------------------------------------------------
__global__ void av_kernel(const float* __restrict__ attn,
                          const float* __restrict__ v,
                          float* __restrict__ x) {
    __shared__ float As[64][33];
    __shared__ float Vs[32][65];
    const int bh = blockIdx.y;
    const int b = bh >> 4, h = bh & 15;
    const int q0 = blockIdx.x * 64;
    const int tid = threadIdx.x;
    const int tx = tid & 15, ty = tid >> 4;

    const float* ab = attn + ((size_t)bh * S_ + q0) * S_;
    const float* vb = v + (size_t)b * S_ * W_ + h * DH_;

    float acc[4][4] = {};
    for (int k0 = 0; k0 < S_; k0 += 32) {
        #pragma unroll
        for (int idx = tid; idx < 64 * 32; idx += 256) {
            int m = idx >> 5, kk = idx & 31;
            As[m][kk] = ab[(size_t)m * S_ + k0 + kk];
        }
        #pragma unroll
        for (int idx = tid; idx < 32 * 64; idx += 256) {
            int kk = idx >> 6, n = idx & 63;
            Vs[kk][n] = vb[(size_t)(k0 + kk) * W_ + n];
        }
        __syncthreads();
        #pragma unroll
        for (int kk = 0; kk < 32; kk++) {
            float a[4], c[4];
            #pragma unroll
            for (int i = 0; i < 4; i++) a[i] = As[ty * 4 + i][kk];
            #pragma unroll
            for (int j = 0; j < 4; j++) c[j] = Vs[kk][tx * 4 + j];
            #pragma unroll
            for (int i = 0; i < 4; i++)
                #pragma unroll
                for (int j = 0; j < 4; j++)
                    acc[i][j] += a[i] * c[j];
        }
        __syncthreads();
    }

    float* xb = x + ((size_t)(b * S_ + q0)) * W_ + h * DH_;
    #pragma unroll
    for (int i = 0; i < 4; i++)
        #pragma unroll
        for (int j = 0; j < 4; j++)
            xb[(size_t)(ty * 4 + i) * W_ + tx * 4 + j] = acc[i][j];
}

// ---------------------------------------------------------------------------
extern "C" void kernel_launch(void* const* d_in, const int* in_sizes, int n_in,
                              void* d_out, int out_size) {
    const float* inp  = (const float*)d_in[0];
    const int*   mask = (const int*)  d_in[1];
    const float* wq   = (const float*)d_in[2];
    const float* bq   = (const float*)d_in[3];
    const float* wk   = (const float*)d_in[4];
    const float* bk   = (const float*)d_in[5];
    const float* wv   = (const float*)d_in[6];
    const float* bv   = (const float*)d_in[7];
    const float* wo   = (const float*)d_in[8];
    const float* bo   = (const float*)d_in[9];
    float* out = (float*)d_out;

    float *q, *k, *v, *x, *qk;
    cudaGetSymbolAddress((void**)&q,  g_q);
    cudaGetSymbolAddress((void**)&k,  g_k);
    cudaGetSymbolAddress((void**)&v,  g_v);
    cudaGetSymbolAddress((void**)&x,  g_x);
    cudaGetSymbolAddress((void**)&qk, g_qk);

    dim3 gemm_grid(W_ / 64, M_ / 64);   // (16, 64)
    // Q, K, V projections
    gemm_bias_kernel<<<gemm_grid, 256>>>(inp, wq, bq, q, M_, W_, W_);
    gemm_bias_kernel<<<gemm_grid, 256>>>(inp, wk, bk, k, M_, W_, W_);
    gemm_bias_kernel<<<gemm_grid, 256>>>(inp, wv, bv, v, M_, W_, W_);

    // QK^T scores
    dim3 qk_grid(S_ / 64, S_ / 64, B_ * H_);   // (16, 16, 64)
    qk_kernel<<<qk_grid, 256>>>(q, k, qk);

    // head-axis softmax (in place)
    int nthreads = B_ * S_ * S_;
    head_softmax_kernel<<<(nthreads + 255) / 256, 256>>>(mask, qk);

    // attn @ V  (writes transposed straight into [B,S,WIDTH])
    dim3 av_grid(S_ / 64, B_ * H_);   // (16, 64)
    av_kernel<<<av_grid, 256>>>(qk, v, x);

    // output projection
    gemm_bias_kernel<<<gemm_grid, 256>>>(x, wo, bo, out, M_, W_, W_);
}

// round 2
// speedup vs baseline: 1.6673x; 1.6673x over previous
#include <cuda_runtime.h>
#include <cuda_bf16.h>

// MaskedAttention: B=4, S=1024, WIDTH=1024, H=16, DH=64
// softmax over the HEAD axis (axis=1), mask broadcast over heads.

#define B_ 4
#define S_ 1024
#define W_ 1024
#define H_ 16
#define DH_ 64
#define M_ (B_ * S_)          // 4096 rows

// Scratch (device globals: allocation-free rule)
__device__ float g_q[M_ * W_];
__device__ float g_k[M_ * W_];
__device__ float g_v[M_ * W_];
__device__ float g_x[M_ * W_];
__device__ float g_qk[(size_t)B_ * H_ * S_ * S_];   // 256 MB scores/attn

// ---------------------------------------------------------------------------
// GEMM with bias: C[m,n] = sum_k A[m,k] * Wt[n,k] + bias[n]
// 128x128 tile, K-tile 32, 256 threads, 8x8 microtile, float4 smem reads.
// ---------------------------------------------------------------------------
__global__ __launch_bounds__(256) void gemm_bias_kernel(
        const float* __restrict__ A,
        const float* __restrict__ Wt,
        const float* __restrict__ bias,
        float* __restrict__ C,
        int M, int N, int K) {
    __shared__ float As[32][128];
    __shared__ float Ws[32][128];
    const int tid = threadIdx.x;
    const int tx = tid & 15;          // 0..15 -> col group (8 cols)
    const int ty = tid >> 4;          // 0..15 -> row group (8 rows)
    const int row0 = blockIdx.y * 128;
    const int col0 = blockIdx.x * 128;

    float acc[8][8] = {};

    for (int k0 = 0; k0 < K; k0 += 32) {
        // load A tile: 128 rows x 32 k = 1024 float4
        #pragma unroll
        for (int it = 0; it < 4; it++) {
            int idx = tid + it * 256;
            int r = idx >> 3, kv = idx & 7;
            float4 t = *(const float4*)&A[(size_t)(row0 + r) * K + k0 + kv * 4];
            As[kv * 4 + 0][r] = t.x;
            As[kv * 4 + 1][r] = t.y;
            As[kv * 4 + 2][r] = t.z;
            As[kv * 4 + 3][r] = t.w;
        }
        // load W tile: 128 n x 32 k
        #pragma unroll
        for (int it = 0; it < 4; it++) {
            int idx = tid + it * 256;
            int r = idx >> 3, kv = idx & 7;
            float4 t = *(const float4*)&Wt[(size_t)(col0 + r) * K + k0 + kv * 4];
            Ws[kv * 4 + 0][r] = t.x;
            Ws[kv * 4 + 1][r] = t.y;
            Ws[kv * 4 + 2][r] = t.z;
            Ws[kv * 4 + 3][r] = t.w;
        }
        __syncthreads();

        #pragma unroll
        for (int kk = 0; kk < 32; kk++) {
            float4 a0 = *(const float4*)&As[kk][ty * 8];
            float4 a1 = *(const float4*)&As[kk][ty * 8 + 4];
            float4 b0 = *(const float4*)&Ws[kk][tx * 8];
            float4 b1 = *(const float4*)&Ws[kk][tx * 8 + 4];
            float a[8] = {a0.x, a0.y, a0.z, a0.w, a1.x, a1.y, a1.z, a1.w};
            float bv[8] = {b0.x, b0.y, b0.z, b0.w, b1.x, b1.y, b1.z, b1.w};
            #pragma unroll
            for (int i = 0; i < 8; i++)
                #pragma unroll
                for (int j = 0; j < 8; j++)
                    acc[i][j] += a[i] * bv[j];
        }
        __syncthreads();
    }

    // epilogue with bias, float4 stores
    float4 bvec0 = *(const float4*)&bias[col0 + tx * 8];
    float4 bvec1 = *(const float4*)&bias[col0 + tx * 8 + 4];
    #pragma unroll
    for (int i = 0; i < 8; i++) {
        float4 o0, o1;
        o0.x = acc[i][0] + bvec0.x; o0.y = acc[i][1] + bvec0.y;
        o0.z = acc[i][2] + bvec0.z; o0.w = acc[i][3] + bvec0.w;
        o1.x = acc[i][4] + bvec1.x; o1.y = acc[i][5] + bvec1.y;
        o1.z = acc[i][6] + bvec1.z; o1.w = acc[i][7] + bvec1.w;
        float* cp = &C[(size_t)(row0 + ty * 8 + i) * N + col0 + tx * 8];
        *(float4*)cp = o0;
        *(float4*)(cp + 4) = o1;
    }
}

// ---------------------------------------------------------------------------
// QK^T per (b,h): out[bh,i,j] = scale * sum_d Q[b,i,h*64+d] * K[b,j,h*64+d]
// 128x128 tile, D-tile 32 (x2), 256 threads, 8x8 microtile.
// ---------------------------------------------------------------------------
__global__ __launch_bounds__(256) void qk_kernel(
        const float* __restrict__ q,
        const float* __restrict__ k,
        float* __restrict__ out) {
    __shared__ float Qs[32][128];
    __shared__ float Ks[32][128];
    const int bh = blockIdx.z;
    const int b = bh >> 4, h = bh & 15;
    const int i0 = blockIdx.y * 128, j0 = blockIdx.x * 128;
    const int tid = threadIdx.x;
    const int tx = tid & 15, ty = tid >> 4;

    const float* qb = q + (size_t)b * S_ * W_ + h * DH_;
    const float* kb = k + (size_t)b * S_ * W_ + h * DH_;

    float acc[8][8] = {};

    #pragma unroll
    for (int d0 = 0; d0 < DH_; d0 += 32) {
        #pragma unroll
        for (int it = 0; it < 4; it++) {
            int idx = tid + it * 256;
            int r = idx >> 3, dv = idx & 7;
            float4 tq = *(const float4*)&qb[(size_t)(i0 + r) * W_ + d0 + dv * 4];
            Qs[dv * 4 + 0][r] = tq.x;
            Qs[dv * 4 + 1][r] = tq.y;
            Qs[dv * 4 + 2][r] = tq.z;
            Qs[dv * 4 + 3][r] = tq.w;
            float4 tk = *(const float4*)&kb[(size_t)(j0 + r) * W_ + d0 + dv * 4];
            Ks[dv * 4 + 0][r] = tk.x;
            Ks[dv * 4 + 1][r] = tk.y;
            Ks[dv * 4 + 2][r] = tk.z;
            Ks[dv * 4 + 3][r] = tk.w;
        }
        __syncthreads();

        #pragma unroll
        for (int d = 0; d < 32; d++) {
            float4 a0 = *(const float4*)&Qs[d][ty * 8];
            float4 a1 = *(const float4*)&Qs[d][ty * 8 + 4];
            float4 b0 = *(const float4*)&Ks[d][tx * 8];
            float4 b1 = *(const float4*)&Ks[d][tx * 8 + 4];
            float a[8] = {a0.x, a0.y, a0.z, a0.w, a1.x, a1.y, a1.z, a1.w};
            float c[8] = {b0.x, b0.y, b0.z, b0.w, b1.x, b1.y, b1.z, b1.w};
            #pragma unroll
            for (int i = 0; i < 8; i++)
                #pragma unroll
                for (int j = 0; j < 8; j++)
                    acc[i][j] += a[i] * c[j];
        }
        __syncthreads();
    }

    float* ob = out + ((size_t)bh * S_ + i0) * S_ + j0;
    const float scale = 0.125f;   // 1/sqrt(64)
    #pragma unroll
    for (int i = 0; i < 8; i++) {
        float4 o0, o1;
        o0.x = acc[i][0] * scale; o0.y = acc[i][1] * scale;
        o0.z = acc[i][2] * scale; o0.w = acc[i][3] * scale;
        o1.x = acc[i][4] * scale; o1.y = acc[i][5] * scale;
        o1.z = acc[i][6] * scale; o1.w = acc[i][7] * scale;
        float* op = &ob[(size_t)(ty * 8 + i) * S_ + tx * 8];
        *(float4*)op = o0;
        *(float4*)(op + 4) = o1;
    }
}

// ---------------------------------------------------------------------------
// Softmax over the HEAD axis, in place. Vectorized: each thread handles 4
// consecutive k positions for all 16 heads. Masked positions -> uniform 1/16.
// ---------------------------------------------------------------------------
__global__ __launch_bounds__(256) void head_softmax_kernel(
        const int* __restrict__ mask,
        float* __restrict__ qk) {
    const int idx = blockIdx.x * blockDim.x + threadIdx.x;   // over B*S*S/4
    const int b = idx >> 18;                                 // S*S/4 = 2^18
    const int qs4 = idx & ((1 << 18) - 1);
    const size_t base = (size_t)b * H_ * S_ * S_ + (size_t)qs4 * 4;
    const size_t hs = (size_t)S_ * S_;

    int4 mv = ((const int4*)mask)[idx];
    int ms[4] = {mv.x, mv.y, mv.z, mv.w};

    float v[H_][4];
    #pragma unroll
    for (int h = 0; h < H_; h++) {
        float4 t = *(const float4*)&qk[base + h * hs];
        v[h][0] = t.x; v[h][1] = t.y; v[h][2] = t.z; v[h][3] = t.w;
    }

    #pragma unroll
    for (int l = 0; l < 4; l++) {
        if (ms[l] == 0) {
            #pragma unroll
            for (int h = 0; h < H_; h++) v[h][l] = 1.0f / 16.0f;
        } else {
            float mx = v[0][l];
            #pragma unroll
            for (int h = 1; h < H_; h++) mx = fmaxf(mx, v[h][l]);
            float s = 0.0f;
            #pragma unroll
            for (int h = 0; h < H_; h++) {
                v[h][l] = __expf(v[h][l] - mx);
                s += v[h][l];
            }
            float inv = 1.0f / s;
            #pragma unroll
            for (int h = 0; h < H_; h++) v[h][l] *= inv;
        }
    }

    #pragma unroll
    for (int h = 0; h < H_; h++) {
        float4 t = {v[h][0], v[h][1], v[h][2], v[h][3]};
        *(float4*)&qk[base + h * hs] = t;
    }
}

// ---------------------------------------------------------------------------
// AV per (b,h): x[b,q,h*64+d] = sum_k attn[bh,q,k] * v[b,k,h*64+d]
// 128(q) x 64(d) tile, K-tile 32, 256 threads, 8x4 microtile.
// ---------------------------------------------------------------------------
__global__ __launch_bounds__(256) void av_kernel(
        const float* __restrict__ attn,
        const float* __restrict__ v,
        float* __restrict__ x) {
    __shared__ float As[128][32];   // [q][k]
    __shared__ float Vs[32][64];    // [k][d]
    const int bh = blockIdx.y;
    const int b = bh >> 4, h = bh & 15;
    const int q0 = blockIdx.x * 128;
    const int tid = threadIdx.x;
    const int tx = tid & 15;        // d group (4 cols)
    const int ty = tid >> 4;        // q group (8 rows)

    const float* ab = attn + ((size_t)bh * S_ + q0) * S_;
    const float* vb = v + (size_t)b * S_ * W_ + h * DH_;

    float acc[8][4] = {};

    for (int k0 = 0; k0 < S_; k0 += 32) {
        // attn tile: 128 rows x 32 k = 1024 float4 / 4 -> wait: 8 float4/row
        #pragma unroll
        for (int it = 0; it < 4; it++) {
            int idx = tid + it * 256;
            int r = idx >> 3, kv = idx & 7;
            float4 t = *(const float4*)&ab[(size_t)r * S_ + k0 + kv * 4];
            *(float4*)&As[r][kv * 4] = t;
        }
        // v tile: 32 rows x 64 d = 512 float4
        #pragma unroll
        for (int it = 0; it < 2; it++) {
            int idx = tid + it * 256;
            int kk = idx >> 4, dv = idx & 15;
            float4 t = *(const float4*)&vb[(size_t)(k0 + kk) * W_ + dv * 4];
            *(float4*)&Vs[kk][dv * 4] = t;
        }
        __syncthreads();

        #pragma unroll
        for (int kk = 0; kk < 32; kk++) {
            float4 c4 = *(const float4*)&Vs[kk][tx * 4];
            float c[4] = {c4.x, c4.y, c4.z, c4.w};
            #pragma unroll
            for (int i = 0; i < 8; i++) {
                float a = As[ty * 8 + i][kk];
                #pragma unroll
                for (int j = 0; j < 4; j++)
                    acc[i][j] += a * c[j];
            }
        }
        __syncthreads();
    }

    float* xb = x + ((size_t)(b * S_ + q0)) * W_ + h * DH_;
    #pragma unroll
    for (int i = 0; i < 8; i++) {
        float4 t = {acc[i][0], acc[i][1], acc[i][2], acc[i][3]};
        *(float4*)&xb[(size_t)(ty * 8 + i) * W_ + tx * 4] = t;
    }
}

// ---------------------------------------------------------------------------
extern "C" void kernel_launch(void* const* d_in, const int* in_sizes, int n_in,
                              void* d_out, int out_size) {
    const float* inp  = (const float*)d_in[0];
    const int*   mask = (const int*)  d_in[1];
    const float* wq   = (const float*)d_in[2];
    const float* bq   = (const float*)d_in[3];
    const float* wk   = (const float*)d_in[4];
    const float* bk   = (const float*)d_in[5];
    const float* wv   = (const float*)d_in[6];
    const float* bv   = (const float*)d_in[7];
    const float* wo   = (const float*)d_in[8];
    const float* bo   = (const float*)d_in[9];
    float* out = (float*)d_out;

    float *q, *k, *v, *x, *qk;
    cudaGetSymbolAddress((void**)&q,  g_q);
    cudaGetSymbolAddress((void**)&k,  g_k);
    cudaGetSymbolAddress((void**)&v,  g_v);
    cudaGetSymbolAddress((void**)&x,  g_x);
    cudaGetSymbolAddress((void**)&qk, g_qk);

    dim3 gemm_grid(W_ / 128, M_ / 128);   // (8, 32)
    gemm_bias_kernel<<<gemm_grid, 256>>>(inp, wq, bq, q, M_, W_, W_);
    gemm_bias_kernel<<<gemm_grid, 256>>>(inp, wk, bk, k, M_, W_, W_);
    gemm_bias_kernel<<<gemm_grid, 256>>>(inp, wv, bv, v, M_, W_, W_);

    dim3 qk_grid(S_ / 128, S_ / 128, B_ * H_);   // (8, 8, 64)
    qk_kernel<<<qk_grid, 256>>>(q, k, qk);

    int nvec = B_ * S_ * S_ / 4;
    head_softmax_kernel<<<nvec / 256, 256>>>(mask, qk);

    dim3 av_grid(S_ / 128, B_ * H_);   // (8, 64)
    av_kernel<<<av_grid, 256>>>(qk, v, x);

    gemm_bias_kernel<<<gemm_grid, 256>>>(x, wo, bo, out, M_, W_, W_);
}

// round 3
// speedup vs baseline: 3.8926x; 2.3348x over previous
#include <cuda_runtime.h>
#include <cuda_bf16.h>
#include <cstdint>

// MaskedAttention: B=4, S=1024, WIDTH=1024, H=16, DH=64
// softmax over the HEAD axis (axis=1), mask broadcast over heads.
// GEMMs on tensor cores: bf16 3-term split (hi*hi + hi*lo + lo*hi) == ~fp32.

#define B_ 4
#define S_ 1024
#define W_ 1024
#define H_ 16
#define DH_ 64
#define M_ (B_ * S_)          // 4096 rows

// Scratch (device globals: allocation-free rule)
__device__ float g_q[M_ * W_];
__device__ float g_k[M_ * W_];
__device__ float g_vt[B_ * H_ * DH_ * S_];          // V transposed: [bh][d][s]
__device__ float g_x[M_ * W_];
__device__ float g_qk[(size_t)B_ * H_ * S_ * S_];   // 256 MB scores/attn

// ---------------------------------------------------------------------------
// helpers
// ---------------------------------------------------------------------------
__device__ __forceinline__ void mma_bf16(float* c, const uint32_t* a, const uint32_t* b) {
    asm volatile(
        "mma.sync.aligned.m16n8k16.row.col.f32.bf16.bf16.f32 "
        "{%0,%1,%2,%3}, {%4,%5,%6,%7}, {%8,%9}, {%0,%1,%2,%3};"
        : "+f"(c[0]), "+f"(c[1]), "+f"(c[2]), "+f"(c[3])
        : "r"(a[0]), "r"(a[1]), "r"(a[2]), "r"(a[3]), "r"(b[0]), "r"(b[1]));
}

// split (x,y) fp32 pair into packed bf16 hi-pair and lo-pair (x in low 16 bits)
__device__ __forceinline__ void split_pack(float x, float y, uint32_t& hi, uint32_t& lo) {
    __nv_bfloat16 hx = __float2bfloat16(x);
    __nv_bfloat16 hy = __float2bfloat16(y);
    float rx = x - __bfloat162float(hx);
    float ry = y - __bfloat162float(hy);
    __nv_bfloat16 lx = __float2bfloat16(rx);
    __nv_bfloat16 ly = __float2bfloat16(ry);
    __nv_bfloat162 hp = __halves2bfloat162(hx, hy);
    __nv_bfloat162 lp = __halves2bfloat162(lx, ly);
    hi = *reinterpret_cast<uint32_t*>(&hp);
    lo = *reinterpret_cast<uint32_t*>(&lp);
}

// ---------------------------------------------------------------------------
// GEMM core: C[m,n] = scale * (sum_k A[m,k] * B[n,k]) (+ bias[n])
// Block tile: 128(M) x BN(N), K-tile 32. 256 threads = 8 warps (4m x 2n).
// Warp tile: 32(M) x BN/2(N); mma m16n8k16; NT = BN/16 n-tiles per warp.
// Smem rows: 16 uint32 (32 bf16 k) + 4 pad = stride 20 -> conflict-free frags.
// vt_mode: scatter result into vt[bh][d][s] instead of C (for V projection).
// ---------------------------------------------------------------------------
template <int BN, bool VT_MODE>
__device__ __forceinline__ void gemm_core(
        const float* __restrict__ A, int lda,
        const float* __restrict__ B, int ldb,
        float* __restrict__ C, int ldc,
        int K, const float* __restrict__ bias, float scale,
        float* __restrict__ vt) {
    constexpr int NT = BN / 16;
    __shared__ uint32_t AsH[128 * 20];
    __shared__ uint32_t AsL[128 * 20];
    __shared__ uint32_t BsH[BN * 20];
    __shared__ uint32_t BsL[BN * 20];

    const int tid = threadIdx.x;
    const int lane = tid & 31, warp = tid >> 5;
    const int gid = lane >> 2, tig = lane & 3;
    const int wm = warp >> 1, wn = warp & 1;
    const int m0w = wm * 32, n0w = wn * (BN / 2);
    const int row0 = blockIdx.y * 128;
    const int col0 = blockIdx.x * BN;

    float acc[2][NT][4] = {};

    for (int k0 = 0; k0 < K; k0 += 32) {
        // A tile: 128 x 32 floats
        #pragma unroll
        for (int it = 0; it < 4; it++) {
            int idx = tid + it * 256;
            int r = idx >> 3, kv = idx & 7;
            float4 t = *(const float4*)&A[(size_t)(row0 + r) * lda + k0 + kv * 4];
            uint32_t h0, h1, l0, l1;
            split_pack(t.x, t.y, h0, l0);
            split_pack(t.z, t.w, h1, l1);
            AsH[r * 20 + kv * 2] = h0;  AsH[r * 20 + kv * 2 + 1] = h1;
            AsL[r * 20 + kv * 2] = l0;  AsL[r * 20 + kv * 2 + 1] = l1;
        }
        // B tile: BN x 32 floats
        #pragma unroll
        for (int it = 0; it < BN / 32; it++) {
            int idx = tid + it * 256;
            int r = idx >> 3, kv = idx & 7;
            float4 t = *(const float4*)&B[(size_t)(col0 + r) * ldb + k0 + kv * 4];
            uint32_t h0, h1, l0, l1;
            split_pack(t.x, t.y, h0, l0);
            split_pack(t.z, t.w, h1, l1);
            BsH[r * 20 + kv * 2] = h0;  BsH[r * 20 + kv * 2 + 1] = h1;
            BsL[r * 20 + kv * 2] = l0;  BsL[r * 20 + kv * 2 + 1] = l1;
        }
        __syncthreads();

        #pragma unroll
        for (int ks = 0; ks < 2; ks++) {
            const int kb = ks * 8;   // uint32 offset (16 k elements)
            uint32_t ah[2][4], al[2][4], bh[NT][2];
            #pragma unroll
            for (int mi = 0; mi < 2; mi++) {
                int rb = (m0w + mi * 16 + gid) * 20 + kb;
                ah[mi][0] = AsH[rb + tig];
                ah[mi][1] = AsH[rb + 8 * 20 + tig];
                ah[mi][2] = AsH[rb + tig + 4];
                ah[mi][3] = AsH[rb + 8 * 20 + tig + 4];
                al[mi][0] = AsL[rb + tig];
                al[mi][1] = AsL[rb + 8 * 20 + tig];
                al[mi][2] = AsL[rb + tig + 4];
                al[mi][3] = AsL[rb + 8 * 20 + tig + 4];
            }
            #pragma unroll
            for (int ni = 0; ni < NT; ni++) {
                int rb = (n0w + ni * 8 + gid) * 20 + kb;
                bh[ni][0] = BsH[rb + tig];
                bh[ni][1] = BsH[rb + tig + 4];
            }
            // pass 1: hi*hi, pass 2: lo*hi (then Bhi dead)
            #pragma unroll
            for (int mi = 0; mi < 2; mi++)
                #pragma unroll
                for (int ni = 0; ni < NT; ni++)
                    mma_bf16(acc[mi][ni], ah[mi], bh[ni]);
            #pragma unroll
            for (int mi = 0; mi < 2; mi++)
                #pragma unroll
                for (int ni = 0; ni < NT; ni++)
                    mma_bf16(acc[mi][ni], al[mi], bh[ni]);
            // pass 3: hi*lo
            uint32_t bl[NT][2];
            #pragma unroll
            for (int ni = 0; ni < NT; ni++) {
                int rb = (n0w + ni * 8 + gid) * 20 + kb;
                bl[ni][0] = BsL[rb + tig];
                bl[ni][1] = BsL[rb + tig + 4];
            }
            #pragma unroll
            for (int mi = 0; mi < 2; mi++)
                #pragma unroll
                for (int ni = 0; ni < NT; ni++)
                    mma_bf16(acc[mi][ni], ah[mi], bl[ni]);
        }
        __syncthreads();
    }

    // epilogue
    #pragma unroll
    for (int mi = 0; mi < 2; mi++) {
        #pragma unroll
        for (int ni = 0; ni < NT; ni++) {
            int row = row0 + m0w + mi * 16 + gid;
            int col = col0 + n0w + ni * 8 + tig * 2;
            float b0 = bias ? bias[col] : 0.0f;
            float b1 = bias ? bias[col + 1] : 0.0f;
            float v0 = acc[mi][ni][0] * scale + b0;
            float v1 = acc[mi][ni][1] * scale + b1;
            float v2 = acc[mi][ni][2] * scale + b0;
            float v3 = acc[mi][ni][3] * scale + b1;
            if (!VT_MODE) {
                float2 o0 = {v0, v1};
                float2 o1 = {v2, v3};
                *(float2*)&C[(size_t)row * ldc + col] = o0;
                *(float2*)&C[(size_t)(row + 8) * ldc + col] = o1;
            } else {
                // row = b*S + s, col = h*64 + d  ->  vt[(bh*64+d)*S + s]
                int b = row >> 10, s = row & 1023;
                int h = col >> 6, d = col & 63;
                size_t base = ((size_t)(b * 16 + h) * 64 + d) * S_;
                vt[base + s] = v0;
                vt[base + S_ + s] = v1;          // d+1
                vt[base + s + 8] = v2;           // wrong? no: row+8 -> s+8
                vt[base + S_ + s + 8] = v3;
            }
        }
    }
}

// ---------------------------------------------------------------------------
// kernel wrappers
// ---------------------------------------------------------------------------
__global__ __launch_bounds__(256) void proj_kernel(
        const float* __restrict__ A, const float* __restrict__ Wt,
        const float* __restrict__ bias, float* __restrict__ C) {
    gemm_core<128, false>(A, W_, Wt, W_, C, W_, W_, bias, 1.0f, nullptr);
}

__global__ __launch_bounds__(256) void proj_vt_kernel(
        const float* __restrict__ A, const float* __restrict__ Wt,
        const float* __restrict__ bias, float* __restrict__ vt) {
    gemm_core<128, true>(A, W_, Wt, W_, nullptr, W_, W_, bias, 1.0f, vt);
}

__global__ __launch_bounds__(256) void qk_kernel(
        const float* __restrict__ q, const float* __restrict__ k,
        float* __restrict__ out) {
    const int bh = blockIdx.z;
    const int b = bh >> 4, h = bh & 15;
    const float* qb = q + (size_t)b * S_ * W_ + h * DH_;
    const float* kb = k + (size_t)b * S_ * W_ + h * DH_;
    float* ob = out + (size_t)bh * S_ * S_;
    gemm_core<128, false>(qb, W_, kb, W_, ob, S_, DH_, nullptr, 0.125f, nullptr);
}

__global__ __launch_bounds__(256) void av_kernel(
        const float* __restrict__ attn, const float* __restrict__ vt,
        float* __restrict__ x) {
    const int bh = blockIdx.z;
    const int b = bh >> 4, h = bh & 15;
    const float* ab = attn + (size_t)bh * S_ * S_;
    const float* vb = vt + (size_t)bh * DH_ * S_;
    float* xb = x + (size_t)b * S_ * W_ + h * DH_;
    gemm_core<64, false>(ab, S_, vb, S_, xb, W_, S_, nullptr, 1.0f, nullptr);
}

// ---------------------------------------------------------------------------
// Softmax over the HEAD axis, in place. Each thread: 4 k-positions x 16 heads.
// Masked positions -> uniform 1/16 (all-heads logits equal at -1e9).
// ---------------------------------------------------------------------------
__global__ __launch_bounds__(256) void head_softmax_kernel(
        const int* __restrict__ mask,
        float* __restrict__ qk) {
    const int idx = blockIdx.x * blockDim.x + threadIdx.x;   // over B*S*S/4
    const int b = idx >> 18;                                 // S*S/4 = 2^18
    const int qs4 = idx & ((1 << 18) - 1);
    const size_t base = (size_t)b * H_ * S_ * S_ + (size_t)qs4 * 4;
    const size_t hs = (size_t)S_ * S_;

    int4 mv = ((const int4*)mask)[idx];
    int ms[4] = {mv.x, mv.y, mv.z, mv.w};

    float v[H_][4];
    #pragma unroll
    for (int h = 0; h < H_; h++) {
        float4 t = *(const float4*)&qk[base + h * hs];
        v[h][0] = t.x; v[h][1] = t.y; v[h][2] = t.z; v[h][3] = t.w;
    }

    #pragma unroll
    for (int l = 0; l < 4; l++) {
        if (ms[l] == 0) {
            #pragma unroll
            for (int h = 0; h < H_; h++) v[h][l] = 1.0f / 16.0f;
        } else {
            float mx = v[0][l];
            #pragma unroll
            for (int h = 1; h < H_; h++) mx = fmaxf(mx, v[h][l]);
            float s = 0.0f;
            #pragma unroll
            for (int h = 0; h < H_; h++) {
                v[h][l] = __expf(v[h][l] - mx);
                s += v[h][l];
            }
            float inv = 1.0f / s;
            #pragma unroll
            for (int h = 0; h < H_; h++) v[h][l] *= inv;
        }
    }

    #pragma unroll
    for (int h = 0; h < H_; h++) {
        float4 t = {v[h][0], v[h][1], v[h][2], v[h][3]};
        *(float4*)&qk[base + h * hs] = t;
    }
}

// ---------------------------------------------------------------------------
extern "C" void kernel_launch(void* const* d_in, const int* in_sizes, int n_in,
                              void* d_out, int out_size) {
    const float* inp  = (const float*)d_in[0];
    const int*   mask = (const int*)  d_in[1];
    const float* wq   = (const float*)d_in[2];
    const float* bq   = (const float*)d_in[3];
    const float* wk   = (const float*)d_in[4];
    const float* bk   = (const float*)d_in[5];
    const float* wv   = (const float*)d_in[6];
    const float* bv   = (const float*)d_in[7];
    const float* wo   = (const float*)d_in[8];
    const float* bo   = (const float*)d_in[9];
    float* out = (float*)d_out;

    float *q, *k, *vt, *x, *qk;
    cudaGetSymbolAddress((void**)&q,  g_q);
    cudaGetSymbolAddress((void**)&k,  g_k);
    cudaGetSymbolAddress((void**)&vt, g_vt);
    cudaGetSymbolAddress((void**)&x,  g_x);
    cudaGetSymbolAddress((void**)&qk, g_qk);

    dim3 proj_grid(W_ / 128, M_ / 128);   // (8, 32)
    proj_kernel<<<proj_grid, 256>>>(inp, wq, bq, q);
    proj_kernel<<<proj_grid, 256>>>(inp, wk, bk, k);
    proj_vt_kernel<<<proj_grid, 256>>>(inp, wv, bv, vt);

    dim3 qk_grid(S_ / 128, S_ / 128, B_ * H_);   // (8, 8, 64)
    qk_kernel<<<qk_grid, 256>>>(q, k, qk);

    int nvec = B_ * S_ * S_ / 4;
    head_softmax_kernel<<<nvec / 256, 256>>>(mask, qk);

    dim3 av_grid(1, S_ / 128, B_ * H_);   // (1, 8, 64)
    av_kernel<<<av_grid, 256>>>(qk, vt, x);

    proj_kernel<<<proj_grid, 256>>>(x, wo, bo, out);
}